// round 5
// baseline (speedup 1.0000x reference)
#include <cuda_runtime.h>

#define NN 8192
#define FF 128
#define EE 262144
#define METAL 64
#define NOUT 17
#define TWO_N (2*NN)
#define TWO_E (2*EE)
#define KSPLIT 128
#define KCHUNK (TWO_N / KSPLIT)   // 128
#define TPB 256

// ---- scratch (device globals: no allocation allowed) ----
__device__ int   d_cnt[TWO_N];        // in-degree counts (no self-loop)
__device__ int   d_row[TWO_N + 1];    // CSR row starts
__device__ int   d_cur[TWO_N];        // placement cursors
__device__ int   d_srcs[TWO_E];       // CSR src lists (global node ids)
__device__ float d_dinv[TWO_N];
__device__ float d_gv[4][TWO_N];      // g per round
__device__ float d_h[TWO_N];
__device__ float d_res[NN];           // result_inter partials
__device__ float d_wc[FF];            // W1@W2@W3@W4
__device__ float d_c[4];              // c1, c2, c3, b4'

// --------------------------------- setup: cnt=0, res=0, combined weights
__global__ void k_setup(const float* __restrict__ W1, const float* __restrict__ b1,
                        const float* __restrict__ W2, const float* __restrict__ b2,
                        const float* __restrict__ W3, const float* __restrict__ b3,
                        const float* __restrict__ W4, const float* __restrict__ b4) {
    int i = blockIdx.x * blockDim.x + threadIdx.x;
    if (i < TWO_N) d_cnt[i] = 0;
    if (i < NN)    d_res[i] = 0.0f;
    if (blockIdx.x == 0 && threadIdx.x < FF) {
        int f = threadIdx.x;
        float w34[4], w234[8];
#pragma unroll
        for (int c = 0; c < 4; c++)
            w34[c] = W3[c * 2 + 0] * W4[0] + W3[c * 2 + 1] * W4[1];
#pragma unroll
        for (int r = 0; r < 8; r++) {
            float s = 0.0f;
#pragma unroll
            for (int c = 0; c < 4; c++) s += W2[r * 4 + c] * w34[c];
            w234[r] = s;
        }
        float s = 0.0f;
#pragma unroll
        for (int r = 0; r < 8; r++) s += W1[f * 8 + r] * w234[r];
        d_wc[f] = s;
        if (f == 0) {
            float c1 = 0.0f, c2 = 0.0f;
#pragma unroll
            for (int r = 0; r < 8; r++) c1 += b1[r] * w234[r];
#pragma unroll
            for (int c = 0; c < 4; c++) c2 += b2[c] * w34[c];
            d_c[0] = c1;
            d_c[1] = c2;
            d_c[2] = b3[0] * W4[0] + b3[1] * W4[1];
            d_c[3] = b4[0];
        }
    }
}

// ---------------------------------------------- degree count (4 dsts/thread)
__global__ void k_count(const int* __restrict__ ei1, const int* __restrict__ ei2) {
    int t = blockIdx.x * blockDim.x + threadIdx.x;
    const int Q = EE / 4;
    int4 d; int off;
    if (t < Q) { d = ((const int4*)(ei1 + EE))[t];      off = 0;  }
    else       { d = ((const int4*)(ei2 + EE))[t - Q];  off = NN; }
    atomicAdd(&d_cnt[off + d.x], 1);
    atomicAdd(&d_cnt[off + d.y], 1);
    atomicAdd(&d_cnt[off + d.z], 1);
    atomicAdd(&d_cnt[off + d.w], 1);
}

// -------- single-block scan: row starts, cursors, dinv = rsqrt(cnt+1)
__global__ void __launch_bounds__(1024) k_scan() {
    __shared__ int wsum[32];
    const int t = threadIdx.x;
    const int ITEMS = TWO_N / 1024;   // 16
    int base = t * ITEMS;
    int loc[ITEMS], c[ITEMS];
    int s = 0;
#pragma unroll
    for (int j = 0; j < ITEMS; j++) {
        c[j] = d_cnt[base + j];
        loc[j] = s;
        s += c[j];
    }
    int lane = t & 31, wid = t >> 5;
    // warp inclusive scan of per-thread totals
    int inc = s;
#pragma unroll
    for (int o = 1; o < 32; o <<= 1) {
        int v = __shfl_up_sync(0xffffffff, inc, o);
        if (lane >= o) inc += v;
    }
    if (lane == 31) wsum[wid] = inc;
    __syncthreads();
    if (wid == 0) {
        int v = wsum[lane];
#pragma unroll
        for (int o = 1; o < 32; o <<= 1) {
            int u = __shfl_up_sync(0xffffffff, v, o);
            if (lane >= o) v += u;
        }
        wsum[lane] = v;
    }
    __syncthreads();
    int excl = inc - s + (wid > 0 ? wsum[wid - 1] : 0);
#pragma unroll
    for (int j = 0; j < ITEMS; j++) {
        int st = excl + loc[j];
        d_row[base + j] = st;
        d_cur[base + j] = st;
        d_dinv[base + j] = rsqrtf((float)(c[j] + 1));
    }
    if (t == 0) d_row[TWO_N] = TWO_E;
}

// ------------------------------- CSR placement (4 edges/thread)
__global__ void k_place(const int* __restrict__ ei1, const int* __restrict__ ei2) {
    int t = blockIdx.x * blockDim.x + threadIdx.x;
    const int Q = EE / 4;
    int4 s4, d4; int off;
    if (t < Q) {
        s4 = ((const int4*)ei1)[t];       d4 = ((const int4*)(ei1 + EE))[t];       off = 0;
    } else {
        s4 = ((const int4*)ei2)[t - Q];   d4 = ((const int4*)(ei2 + EE))[t - Q];   off = NN;
    }
    int p0 = atomicAdd(&d_cur[off + d4.x], 1);
    int p1 = atomicAdd(&d_cur[off + d4.y], 1);
    int p2 = atomicAdd(&d_cur[off + d4.z], 1);
    int p3 = atomicAdd(&d_cur[off + d4.w], 1);
    d_srcs[p0] = off + s4.x;
    d_srcs[p1] = off + s4.y;
    d_srcs[p2] = off + s4.z;
    d_srcs[p3] = off + s4.w;
}

// ----------- g0 = dinv*(x@wc)   (warp per node)
__global__ void k_xwc(const float* __restrict__ x1, const float* __restrict__ x2) {
    __shared__ float swc[FF];
    if (threadIdx.x < FF) swc[threadIdx.x] = d_wc[threadIdx.x];
    __syncthreads();
    int gt = blockIdx.x * blockDim.x + threadIdx.x;
    int i = gt >> 5;
    int lane = gt & 31;
    if (i >= TWO_N) return;
    const float* x = (i < NN) ? (x1 + (size_t)i * FF) : (x2 + (size_t)(i - NN) * FF);
    float4 v = ((const float4*)x)[lane];
    float4 w = ((const float4*)swc)[lane];
    float s = v.x * w.x + v.y * w.y + v.z * w.z + v.w * w.w;
#pragma unroll
    for (int o = 16; o > 0; o >>= 1) s += __shfl_xor_sync(0xffffffff, s, o);
    if (lane == 0) d_gv[0][i] = d_dinv[i] * s;
}

// ---------- pull-based round: warp per node, CSR gather, fused node update
__global__ void k_round(int r) {
    int gt = blockIdx.x * blockDim.x + threadIdx.x;
    int i = gt >> 5;
    int lane = gt & 31;
    if (i >= TWO_N) return;
    const float* g = d_gv[r];
    int s0 = d_row[i], s1 = d_row[i + 1];
    float acc = 0.0f;
    for (int e = s0 + lane; e < s1; e += 32)
        acc += g[d_srcs[e]];
#pragma unroll
    for (int o = 16; o > 0; o >>= 1) acc += __shfl_xor_sync(0xffffffff, acc, o);
    if (lane == 0) {
        float dv = d_dinv[i];
        float ytot = acc + g[i];           // self-loop
        if (r < 3) d_gv[r + 1][i] = dv * (dv * ytot + d_c[r]);
        else       d_h[i] = dv * ytot + d_c[3];
    }
}

// ---- big GEMV: res[j] += sum_k h[k]*Wi[k*N+j] (k-split, streaming reads)
//      block (0,0) also initializes out = bf + meta @ Wf[N:]
__global__ void __launch_bounds__(TPB) k_wi_gemv(
    const float* __restrict__ Wi, const float* __restrict__ meta,
    const float* __restrict__ Wf, const float* __restrict__ bf,
    float* __restrict__ out)
{
    __shared__ float sh[KCHUNK];
    int k0 = blockIdx.y * KCHUNK;
    if (threadIdx.x < KCHUNK) sh[threadIdx.x] = d_h[k0 + threadIdx.x];
    __syncthreads();
    int j4 = blockIdx.x * blockDim.x + threadIdx.x;   // float4 column index
    const float4* Wi4 = (const float4*)Wi;
    float4 acc = make_float4(0.f, 0.f, 0.f, 0.f);
#pragma unroll 8
    for (int kk = 0; kk < KCHUNK; kk++) {
        float c = sh[kk];
        float4 w = __ldcs(&Wi4[(size_t)(k0 + kk) * (NN / 4) + j4]);
        acc.x += c * w.x; acc.y += c * w.y; acc.z += c * w.z; acc.w += c * w.w;
    }
    int j = j4 * 4;
    atomicAdd(&d_res[j + 0], acc.x);
    atomicAdd(&d_res[j + 1], acc.y);
    atomicAdd(&d_res[j + 2], acc.z);
    atomicAdd(&d_res[j + 3], acc.w);
    if (blockIdx.x == 0 && blockIdx.y == 0 && threadIdx.x < NOUT) {
        int jj = threadIdx.x;
        float s = bf[jj];
#pragma unroll 8
        for (int m = 0; m < METAL; m++)
            s += meta[m] * Wf[(size_t)(NN + m) * NOUT + jj];
        out[jj] = s;
    }
}

// ---------------- out += (res + bi) @ Wf[:N]   (bi folded here)
__global__ void k_out_acc(const float* __restrict__ Wf,
                          const float* __restrict__ bi,
                          float* __restrict__ out) {
    int i = blockIdx.x * blockDim.x + threadIdx.x;   // exactly NN threads
    float r = d_res[i] + bi[i];
    float acc[NOUT];
#pragma unroll
    for (int j = 0; j < NOUT; j++) acc[j] = r * Wf[(size_t)i * NOUT + j];
#pragma unroll
    for (int j = 0; j < NOUT; j++) {
#pragma unroll
        for (int o = 16; o > 0; o >>= 1)
            acc[j] += __shfl_xor_sync(0xffffffff, acc[j], o);
    }
    if ((threadIdx.x & 31) == 0) {
#pragma unroll
        for (int j = 0; j < NOUT; j++) atomicAdd(&out[j], acc[j]);
    }
}

// ================================================================= launch
extern "C" void kernel_launch(void* const* d_in, const int* in_sizes, int n_in,
                              void* d_out, int out_size) {
    const float* x1   = (const float*)d_in[0];
    const float* x2   = (const float*)d_in[1];
    const float* meta = (const float*)d_in[2];
    const float* W1   = (const float*)d_in[3];
    const float* b1   = (const float*)d_in[4];
    const float* W2   = (const float*)d_in[5];
    const float* b2   = (const float*)d_in[6];
    const float* W3   = (const float*)d_in[7];
    const float* b3   = (const float*)d_in[8];
    const float* W4   = (const float*)d_in[9];
    const float* b4   = (const float*)d_in[10];
    const float* Wi   = (const float*)d_in[11];
    const float* bi   = (const float*)d_in[12];
    const float* Wf   = (const float*)d_in[13];
    const float* bf   = (const float*)d_in[14];
    const int*   ei1  = (const int*)d_in[15];
    const int*   ei2  = (const int*)d_in[16];
    float* out = (float*)d_out;

    k_setup<<<TWO_N / TPB, TPB>>>(W1, b1, W2, b2, W3, b3, W4, b4);
    k_count<<<(TWO_E / 4) / TPB, TPB>>>(ei1, ei2);
    k_scan<<<1, 1024>>>();
    k_place<<<(TWO_E / 4) / TPB, TPB>>>(ei1, ei2);
    k_xwc<<<(TWO_N * 32) / TPB, TPB>>>(x1, x2);
    for (int r = 0; r < 4; r++)
        k_round<<<(TWO_N * 32) / TPB, TPB>>>(r);
    {
        dim3 grid(NN / (TPB * 4), KSPLIT);
        k_wi_gemv<<<grid, TPB>>>(Wi, meta, Wf, bf, out);
    }
    k_out_acc<<<NN / TPB, TPB>>>(Wf, bi, out);
}